// round 6
// baseline (speedup 1.0000x reference)
#include <cuda_runtime.h>
#include <cuda_bf16.h>

#define NODES 100000
#define FEAT  16
#define HID   32

// Scratch (allocation-free rule: __device__ globals)
__device__ __align__(16) float g_deg[NODES];
__device__ __align__(16) float g_dis[NODES];
__device__ __align__(16) float g_tx1[NODES * FEAT];

// ---------------------------------------------------------------- zero scratch
__global__ void k_zero(int n16, int n) {
    int i = blockIdx.x * blockDim.x + threadIdx.x;
    if (i < n16) g_tx1[i] = 0.0f;
    if (i < n)   g_deg[i] = 0.0f;
}

// ---------------------------------------------------------------- deg = segsum(w, src)
// NOTE: edge_index is int32 in the actual buffer (JAX x64-disabled downcasts
// the reference's jnp.int64) — reading it as int64 was the R5 illegal access.
__global__ void k_deg(const int* __restrict__ src,
                      const float* __restrict__ w, int E) {
    int e = blockIdx.x * blockDim.x + threadIdx.x;
    if (e < E) {
        atomicAdd(&g_deg[src[e]], __ldg(&w[e]));
    }
}

// ---------------------------------------------------------------- dis = rsqrt(deg)
__global__ void k_dis(int n) {
    int i = blockIdx.x * blockDim.x + threadIdx.x;
    if (i < n) {
        float d = g_deg[i];
        g_dis[i] = (d > 0.0f) ? rsqrtf(fmaxf(d, 1e-12f)) : 0.0f;
    }
}

// ---------------------------------------------------------------- tx1 = segsum(lhat * x[src], dst)
__global__ void k_scatter(const int* __restrict__ src,
                          const int* __restrict__ dst,
                          const float* __restrict__ w,
                          const float4* __restrict__ x4, int E) {
    int e = blockIdx.x * blockDim.x + threadIdx.x;
    if (e >= E) return;
    int s = src[e];
    int d = dst[e];
    float lw = -__ldg(&g_dis[s]) * __ldg(&w[e]) * __ldg(&g_dis[d]);
    const float4* xs = x4 + (size_t)s * 4;   // x row = 16 floats; x (6.4MB) is L2-resident
    float* o = g_tx1 + (size_t)d * FEAT;
#pragma unroll
    for (int q = 0; q < 4; q++) {
        float4 v = __ldg(&xs[q]);
        // Vector reduction (PTX ISA 8.1+, sm_90+): 1 LTS op instead of 4 scalar REDs
        asm volatile("red.global.add.v4.f32 [%0], {%1, %2, %3, %4};"
                     :: "l"(o + q * 4),
                        "f"(lw * v.x), "f"(lw * v.y), "f"(lw * v.z), "f"(lw * v.w)
                     : "memory");
    }
}

// ---------------------------------------------------------------- per-node gates + readout
// Weights staged into SMEM per block (no __constant__: graph memcpy to the
// constant address space is unsupported -> was the R3 runtime failure).
__global__ void __launch_bounds__(128) k_node(const float4* __restrict__ x4,
                                              const float* __restrict__ Wxz,   // [2][16][32]
                                              const float* __restrict__ bxz,
                                              const float* __restrict__ bhz,
                                              const float* __restrict__ Wxh,   // [2][16][32]
                                              const float* __restrict__ bxh,
                                              const float* __restrict__ bhh,
                                              const float* __restrict__ Wlin,  // [32]
                                              const float* __restrict__ blin,  // [1]
                                              float* __restrict__ out, int n) {
    __shared__ float sWz[2 * FEAT * HID];   // 1024
    __shared__ float sWh[2 * FEAT * HID];   // 1024
    __shared__ float sbz[HID];              // bxz + bhz
    __shared__ float sbh[HID];              // bxh + bhh
    __shared__ float sWl[HID];
    __shared__ float sbl;

    int t = threadIdx.x;
    for (int k = t; k < 2 * FEAT * HID; k += 128) {
        sWz[k] = __ldg(&Wxz[k]);
        sWh[k] = __ldg(&Wxh[k]);
    }
    if (t < HID) {
        sbz[t] = __ldg(&bxz[t]) + __ldg(&bhz[t]);
        sbh[t] = __ldg(&bxh[t]) + __ldg(&bhh[t]);
        sWl[t] = __ldg(&Wlin[t]);
    }
    if (t == 0) sbl = __ldg(&blin[0]);
    __syncthreads();

    int i = blockIdx.x * blockDim.x + t;
    if (i >= n) return;

    float xr[FEAT], tr[FEAT];
#pragma unroll
    for (int q = 0; q < 4; q++) {
        float4 v = __ldg(&x4[(size_t)i * 4 + q]);
        xr[4 * q + 0] = v.x; xr[4 * q + 1] = v.y; xr[4 * q + 2] = v.z; xr[4 * q + 3] = v.w;
        float4 tv = reinterpret_cast<const float4*>(g_tx1)[(size_t)i * 4 + q];
        tr[4 * q + 0] = tv.x; tr[4 * q + 1] = tv.y; tr[4 * q + 2] = tv.z; tr[4 * q + 3] = tv.w;
    }

    float az[HID], ah[HID];
#pragma unroll
    for (int h = 0; h < HID; h++) {
        az[h] = sbz[h];
        ah[h] = sbh[h];
    }

#pragma unroll
    for (int c = 0; c < FEAT; c++) {
        float xc = xr[c];
        float tc = tr[c];
        const float* wz0 = sWz + c * HID;               // W[0][c][:]
        const float* wz1 = sWz + FEAT * HID + c * HID;  // W[1][c][:]
        const float* wh0 = sWh + c * HID;
        const float* wh1 = sWh + FEAT * HID + c * HID;
#pragma unroll
        for (int h = 0; h < HID; h++) {
            az[h] = fmaf(xc, wz0[h], az[h]);
            az[h] = fmaf(tc, wz1[h], az[h]);
            ah[h] = fmaf(xc, wh0[h], ah[h]);
            ah[h] = fmaf(tc, wh1[h], ah[h]);
        }
    }

    float o = sbl;
#pragma unroll
    for (int h = 0; h < HID; h++) {
        float z  = 1.0f / (1.0f + __expf(-az[h]));      // sigmoid
        float e2 = __expf(2.0f * ah[h]);                // tanh(x) = 1 - 2/(e^{2x}+1)
        float th = 1.0f - 2.0f / (e2 + 1.0f);
        float v  = (1.0f - z) * th;                     // H_new = (1-Z)*H_tilde  (H == 0)
        v = fmaxf(v, 0.0f);                             // relu
        o = fmaf(v, sWl[h], o);                         // @ W_lin
    }
    out[i] = o;
}

// ---------------------------------------------------------------- launch
//
// Algebra (reference runs ONE GRU step from H = 0):
//   _cheb(H, *) = bias only;  H*R = 0 -> _cheb(H*R, W_hh) = b_hh
//   H_new = Z*H + (1-Z)*H_tilde = (1-Z)*H_tilde
// => R, W_hz, W_hr, W_hh, W_xr/b_xr weight matrices are dead; only W_xz, W_xh,
//    biases bxz/bhz/bxh/bhh, and W_lin/b_lin matter.
//
// Input order (metadata): 0 x, 1 edge_index, 2 edge_weight, 3 W_xz, 4 b_xz,
// 5 W_hz, 6 b_hz, 7 W_xr, 8 b_xr, 9 W_hr, 10 b_hr, 11 W_xh, 12 b_xh,
// 13 W_hh, 14 b_hh, 15 W_lin, 16 b_lin
extern "C" void kernel_launch(void* const* d_in, const int* in_sizes, int n_in,
                              void* d_out, int out_size) {
    const float* x  = (const float*)d_in[0];
    const int*   ei = (const int*)d_in[1];    // int32 in practice (JAX x64 off)
    const float* ew = (const float*)d_in[2];

    int n = in_sizes[0] / FEAT;     // 100000
    int E = in_sizes[2];            // 3200000
    const int* src = ei;            // edge_index[0]
    const int* dst = ei + E;        // edge_index[1]

    const int T = 256;
    k_zero   <<<(n * FEAT + T - 1) / T, T>>>(n * FEAT, n);
    k_deg    <<<(E + T - 1) / T, T>>>(src, ew, E);
    k_dis    <<<(n + T - 1) / T, T>>>(n);
    k_scatter<<<(E + T - 1) / T, T>>>(src, dst, ew, (const float4*)x, E);
    k_node   <<<(n + 127) / 128, 128>>>((const float4*)x,
                                        (const float*)d_in[3],  (const float*)d_in[4],
                                        (const float*)d_in[6],  (const float*)d_in[11],
                                        (const float*)d_in[12], (const float*)d_in[14],
                                        (const float*)d_in[15], (const float*)d_in[16],
                                        (float*)d_out, n);
}

// round 7
// speedup vs baseline: 1.0613x; 1.0613x over previous
#include <cuda_runtime.h>
#include <cuda_bf16.h>

#define NODES 100000
#define FEAT  16
#define HID   32

// Scratch (allocation-free rule: __device__ globals)
__device__ __align__(16) float g_deg[NODES];
__device__ __align__(16) float g_dis[NODES];
__device__ __align__(16) float g_xs [NODES * FEAT];   // x'[i] = dis[i] * x[i]
__device__ __align__(16) float g_u  [NODES * FEAT];   // u[d] = sum_e w * x'[src]

// ---------------------------------------------------------------- zero scratch
__global__ void k_zero(int n16, int n) {
    int i = blockIdx.x * blockDim.x + threadIdx.x;
    if (i < n16) g_u[i] = 0.0f;
    if (i < n)   g_deg[i] = 0.0f;
}

// ---------------------------------------------------------------- deg = segsum(w, src)
__global__ void k_deg(const int* __restrict__ src,
                      const float* __restrict__ w, int E) {
    int e = blockIdx.x * blockDim.x + threadIdx.x;
    if (e < E) {
        atomicAdd(&g_deg[src[e]], __ldg(&w[e]));
    }
}

// ---------------------------------------------------------------- dis = rsqrt(deg); x' = dis * x
__global__ void k_dis_scale(const float4* __restrict__ x4, int n) {
    int i = blockIdx.x * blockDim.x + threadIdx.x;
    if (i >= n) return;
    float d  = g_deg[i];
    float di = (d > 0.0f) ? rsqrtf(fmaxf(d, 1e-12f)) : 0.0f;
    g_dis[i] = di;
    float4* xs4 = reinterpret_cast<float4*>(g_xs) + (size_t)i * 4;
#pragma unroll
    for (int q = 0; q < 4; q++) {
        float4 v = __ldg(&x4[(size_t)i * 4 + q]);
        v.x *= di; v.y *= di; v.z *= di; v.w *= di;
        xs4[q] = v;
    }
}

// ---------------------------------------------------------------- u[d] += w * x'[src]
// dis factors are algebraically hoisted OUT of the edge loop:
//   lhat_w*x[s] = -dis[d] * ( w * (dis[s]*x[s]) )  -> dis[s] folded into x',
//   -dis[d] applied per-node in k_node. Saves 2 random L2 loads per edge.
__global__ void k_scatter(const int* __restrict__ src,
                          const int* __restrict__ dst,
                          const float* __restrict__ w, int E) {
    int e = blockIdx.x * blockDim.x + threadIdx.x;
    if (e >= E) return;
    int s = src[e];
    int d = dst[e];
    float we = __ldg(&w[e]);
    const float4* xs = reinterpret_cast<const float4*>(g_xs) + (size_t)s * 4;
    float* o = g_u + (size_t)d * FEAT;
#pragma unroll
    for (int q = 0; q < 4; q++) {
        float4 v = __ldg(&xs[q]);
        // Vector reduction (PTX ISA 8.1+, sm_90+): 1 LTS op instead of 4 scalar REDs
        asm volatile("red.global.add.v4.f32 [%0], {%1, %2, %3, %4};"
                     :: "l"(o + q * 4),
                        "f"(we * v.x), "f"(we * v.y), "f"(we * v.z), "f"(we * v.w)
                     : "memory");
    }
}

// ---------------------------------------------------------------- per-node gates + readout
// tx1[i] = -dis[i] * u[i]; then the two live Cheb GEMVs + gate math + linear.
__global__ void __launch_bounds__(128) k_node(const float4* __restrict__ x4,
                                              const float* __restrict__ Wxz,   // [2][16][32]
                                              const float* __restrict__ bxz,
                                              const float* __restrict__ bhz,
                                              const float* __restrict__ Wxh,   // [2][16][32]
                                              const float* __restrict__ bxh,
                                              const float* __restrict__ bhh,
                                              const float* __restrict__ Wlin,  // [32]
                                              const float* __restrict__ blin,  // [1]
                                              float* __restrict__ out, int n) {
    __shared__ __align__(16) float sWz[2 * FEAT * HID];   // 1024
    __shared__ __align__(16) float sWh[2 * FEAT * HID];   // 1024
    __shared__ float sbz[HID];              // bxz + bhz
    __shared__ float sbh[HID];              // bxh + bhh
    __shared__ float sWl[HID];
    __shared__ float sbl;

    int t = threadIdx.x;
    for (int k = t; k < 2 * FEAT * HID; k += 128) {
        sWz[k] = __ldg(&Wxz[k]);
        sWh[k] = __ldg(&Wxh[k]);
    }
    if (t < HID) {
        sbz[t] = __ldg(&bxz[t]) + __ldg(&bhz[t]);
        sbh[t] = __ldg(&bxh[t]) + __ldg(&bhh[t]);
        sWl[t] = __ldg(&Wlin[t]);
    }
    if (t == 0) sbl = __ldg(&blin[0]);
    __syncthreads();

    int i = blockIdx.x * blockDim.x + t;
    if (i >= n) return;

    float ndis = -g_dis[i];

    float xr[FEAT], tr[FEAT];
#pragma unroll
    for (int q = 0; q < 4; q++) {
        float4 v = __ldg(&x4[(size_t)i * 4 + q]);
        xr[4 * q + 0] = v.x; xr[4 * q + 1] = v.y; xr[4 * q + 2] = v.z; xr[4 * q + 3] = v.w;
        float4 tv = reinterpret_cast<const float4*>(g_u)[(size_t)i * 4 + q];
        tr[4 * q + 0] = ndis * tv.x; tr[4 * q + 1] = ndis * tv.y;
        tr[4 * q + 2] = ndis * tv.z; tr[4 * q + 3] = ndis * tv.w;
    }

    float az[HID], ah[HID];
#pragma unroll
    for (int h = 0; h < HID; h++) {
        az[h] = sbz[h];
        ah[h] = sbh[h];
    }

    const float4* sWz4 = reinterpret_cast<const float4*>(sWz);
    const float4* sWh4 = reinterpret_cast<const float4*>(sWh);
#pragma unroll
    for (int c = 0; c < FEAT; c++) {
        float xc = xr[c];
        float tc = tr[c];
        int r0 = (c * HID) / 4;                  // W[0][c][:] in float4s
        int r1 = ((FEAT + c) * HID) / 4;         // W[1][c][:]
#pragma unroll
        for (int h4 = 0; h4 < HID / 4; h4++) {
            float4 a = sWz4[r0 + h4];
            float4 b = sWz4[r1 + h4];
            float4 p = sWh4[r0 + h4];
            float4 q = sWh4[r1 + h4];
            int h = h4 * 4;
            az[h+0] = fmaf(xc, a.x, fmaf(tc, b.x, az[h+0]));
            az[h+1] = fmaf(xc, a.y, fmaf(tc, b.y, az[h+1]));
            az[h+2] = fmaf(xc, a.z, fmaf(tc, b.z, az[h+2]));
            az[h+3] = fmaf(xc, a.w, fmaf(tc, b.w, az[h+3]));
            ah[h+0] = fmaf(xc, p.x, fmaf(tc, q.x, ah[h+0]));
            ah[h+1] = fmaf(xc, p.y, fmaf(tc, q.y, ah[h+1]));
            ah[h+2] = fmaf(xc, p.z, fmaf(tc, q.z, ah[h+2]));
            ah[h+3] = fmaf(xc, p.w, fmaf(tc, q.w, ah[h+3]));
        }
    }

    float o = sbl;
#pragma unroll
    for (int h = 0; h < HID; h++) {
        float z  = 1.0f / (1.0f + __expf(-az[h]));      // sigmoid
        float e2 = __expf(2.0f * ah[h]);                // tanh(x) = 1 - 2/(e^{2x}+1)
        float th = 1.0f - 2.0f / (e2 + 1.0f);
        float v  = (1.0f - z) * th;                     // H_new = (1-Z)*H_tilde  (H == 0)
        v = fmaxf(v, 0.0f);                             // relu
        o = fmaf(v, sWl[h], o);                         // @ W_lin
    }
    out[i] = o;
}

// ---------------------------------------------------------------- launch
//
// Algebra (reference runs ONE GRU step from H = 0):
//   _cheb(H, *) = bias only;  H*R = 0 -> _cheb(H*R, W_hh) = b_hh
//   H_new = (1-Z)*H_tilde
// => only W_xz, W_xh, biases bxz/bhz/bxh/bhh, W_lin/b_lin are live.
//
// Input order: 0 x, 1 edge_index(int32), 2 edge_weight, 3 W_xz, 4 b_xz,
// 5 W_hz, 6 b_hz, 7 W_xr, 8 b_xr, 9 W_hr, 10 b_hr, 11 W_xh, 12 b_xh,
// 13 W_hh, 14 b_hh, 15 W_lin, 16 b_lin
extern "C" void kernel_launch(void* const* d_in, const int* in_sizes, int n_in,
                              void* d_out, int out_size) {
    const float* x  = (const float*)d_in[0];
    const int*   ei = (const int*)d_in[1];
    const float* ew = (const float*)d_in[2];

    int n = in_sizes[0] / FEAT;     // 100000
    int E = in_sizes[2];            // 3200000
    const int* src = ei;            // edge_index[0]
    const int* dst = ei + E;        // edge_index[1]

    const int T = 256;
    k_zero     <<<(n * FEAT + T - 1) / T, T>>>(n * FEAT, n);
    k_deg      <<<(E + T - 1) / T, T>>>(src, ew, E);
    k_dis_scale<<<(n + T - 1) / T, T>>>((const float4*)x, n);
    k_scatter  <<<(E + T - 1) / T, T>>>(src, dst, ew, E);
    k_node     <<<(n + 127) / 128, 128>>>((const float4*)x,
                                          (const float*)d_in[3],  (const float*)d_in[4],
                                          (const float*)d_in[6],  (const float*)d_in[11],
                                          (const float*)d_in[12], (const float*)d_in[14],
                                          (const float*)d_in[15], (const float*)d_in[16],
                                          (float*)d_out, n);
}

// round 8
// speedup vs baseline: 1.3903x; 1.3100x over previous
#include <cuda_runtime.h>
#include <cuda_bf16.h>

#define NODES 100000
#define FEAT  16
#define HID   32

// Scratch (allocation-free rule: __device__ globals)
__device__ __align__(16) float g_deg[NODES];
__device__ __align__(16) float g_dis[NODES];
__device__ __align__(16) float g_xs [NODES * FEAT];   // x'[i] = dis[i] * x[i]
__device__ __align__(16) float g_u  [NODES * FEAT];   // u[d] = sum_e w * x'[src]

// ---------------------------------------------------------------- zero scratch
__global__ void k_zero(int n16, int n) {
    int i = blockIdx.x * blockDim.x + threadIdx.x;
    if (i < n16) g_u[i] = 0.0f;
    if (i < n)   g_deg[i] = 0.0f;
}

// ---------------------------------------------------------------- deg = segsum(w, src)
__global__ void k_deg(const int* __restrict__ src,
                      const float* __restrict__ w, int E) {
    int e = blockIdx.x * blockDim.x + threadIdx.x;
    if (e < E) {
        atomicAdd(&g_deg[src[e]], __ldg(&w[e]));
    }
}

// ---------------------------------------------------------------- dis = rsqrt(deg); x' = dis * x
__global__ void k_dis_scale(const float4* __restrict__ x4, int n) {
    int i = blockIdx.x * blockDim.x + threadIdx.x;
    if (i >= n) return;
    float d  = g_deg[i];
    float di = (d > 0.0f) ? rsqrtf(fmaxf(d, 1e-12f)) : 0.0f;
    g_dis[i] = di;
    float4* xs4 = reinterpret_cast<float4*>(g_xs) + (size_t)i * 4;
#pragma unroll
    for (int q = 0; q < 4; q++) {
        float4 v = __ldg(&x4[(size_t)i * 4 + q]);
        v.x *= di; v.y *= di; v.z *= di; v.w *= di;
        xs4[q] = v;
    }
}

// ---------------------------------------------------------------- u[d] += w * x'[src]
// Cooperative scatter: 4 lanes per edge, lane j owns 16B chunk j of the 64B row.
// Warp footprint per instruction = 8 rows (not 32) -> ~1 L1tex wavefront per
// edge for the gather and 1 for the RED (was 4+4). Metadata reads are
// 4-way-redundant but sector-broadcast (free).
__global__ void k_scatter(const int* __restrict__ src,
                          const int* __restrict__ dst,
                          const float* __restrict__ w, long long NT) {
    long long tid = (long long)blockIdx.x * blockDim.x + threadIdx.x;
    if (tid >= NT) return;
    int e = (int)(tid >> 2);
    int j = (int)(tid & 3);
    int s = __ldg(&src[e]);
    int d = __ldg(&dst[e]);
    float we = __ldg(&w[e]);
    float4 v = __ldg(reinterpret_cast<const float4*>(g_xs) + (size_t)s * 4 + j);
    float* o = g_u + (size_t)d * FEAT + j * 4;
    asm volatile("red.global.add.v4.f32 [%0], {%1, %2, %3, %4};"
                 :: "l"(o),
                    "f"(we * v.x), "f"(we * v.y), "f"(we * v.z), "f"(we * v.w)
                 : "memory");
}

// ---------------------------------------------------------------- per-node gates + readout
// tx1[i] = -dis[i] * u[i]; then the two live Cheb GEMVs + gate math + linear.
__global__ void __launch_bounds__(128) k_node(const float4* __restrict__ x4,
                                              const float* __restrict__ Wxz,   // [2][16][32]
                                              const float* __restrict__ bxz,
                                              const float* __restrict__ bhz,
                                              const float* __restrict__ Wxh,   // [2][16][32]
                                              const float* __restrict__ bxh,
                                              const float* __restrict__ bhh,
                                              const float* __restrict__ Wlin,  // [32]
                                              const float* __restrict__ blin,  // [1]
                                              float* __restrict__ out, int n) {
    __shared__ __align__(16) float sWz[2 * FEAT * HID];   // 1024
    __shared__ __align__(16) float sWh[2 * FEAT * HID];   // 1024
    __shared__ float sbz[HID];              // bxz + bhz
    __shared__ float sbh[HID];              // bxh + bhh
    __shared__ float sWl[HID];
    __shared__ float sbl;

    int t = threadIdx.x;
    for (int k = t; k < 2 * FEAT * HID; k += 128) {
        sWz[k] = __ldg(&Wxz[k]);
        sWh[k] = __ldg(&Wxh[k]);
    }
    if (t < HID) {
        sbz[t] = __ldg(&bxz[t]) + __ldg(&bhz[t]);
        sbh[t] = __ldg(&bxh[t]) + __ldg(&bhh[t]);
        sWl[t] = __ldg(&Wlin[t]);
    }
    if (t == 0) sbl = __ldg(&blin[0]);
    __syncthreads();

    int i = blockIdx.x * blockDim.x + t;
    if (i >= n) return;

    float ndis = -g_dis[i];

    float xr[FEAT], tr[FEAT];
#pragma unroll
    for (int q = 0; q < 4; q++) {
        float4 v = __ldg(&x4[(size_t)i * 4 + q]);
        xr[4 * q + 0] = v.x; xr[4 * q + 1] = v.y; xr[4 * q + 2] = v.z; xr[4 * q + 3] = v.w;
        float4 tv = reinterpret_cast<const float4*>(g_u)[(size_t)i * 4 + q];
        tr[4 * q + 0] = ndis * tv.x; tr[4 * q + 1] = ndis * tv.y;
        tr[4 * q + 2] = ndis * tv.z; tr[4 * q + 3] = ndis * tv.w;
    }

    float az[HID], ah[HID];
#pragma unroll
    for (int h = 0; h < HID; h++) {
        az[h] = sbz[h];
        ah[h] = sbh[h];
    }

    const float4* sWz4 = reinterpret_cast<const float4*>(sWz);
    const float4* sWh4 = reinterpret_cast<const float4*>(sWh);
#pragma unroll
    for (int c = 0; c < FEAT; c++) {
        float xc = xr[c];
        float tc = tr[c];
        int r0 = (c * HID) / 4;                  // W[0][c][:] in float4s
        int r1 = ((FEAT + c) * HID) / 4;         // W[1][c][:]
#pragma unroll
        for (int h4 = 0; h4 < HID / 4; h4++) {
            float4 a = sWz4[r0 + h4];
            float4 b = sWz4[r1 + h4];
            float4 p = sWh4[r0 + h4];
            float4 q = sWh4[r1 + h4];
            int h = h4 * 4;
            az[h+0] = fmaf(xc, a.x, fmaf(tc, b.x, az[h+0]));
            az[h+1] = fmaf(xc, a.y, fmaf(tc, b.y, az[h+1]));
            az[h+2] = fmaf(xc, a.z, fmaf(tc, b.z, az[h+2]));
            az[h+3] = fmaf(xc, a.w, fmaf(tc, b.w, az[h+3]));
            ah[h+0] = fmaf(xc, p.x, fmaf(tc, q.x, ah[h+0]));
            ah[h+1] = fmaf(xc, p.y, fmaf(tc, q.y, ah[h+1]));
            ah[h+2] = fmaf(xc, p.z, fmaf(tc, q.z, ah[h+2]));
            ah[h+3] = fmaf(xc, p.w, fmaf(tc, q.w, ah[h+3]));
        }
    }

    float o = sbl;
#pragma unroll
    for (int h = 0; h < HID; h++) {
        float z  = 1.0f / (1.0f + __expf(-az[h]));      // sigmoid
        float e2 = __expf(2.0f * ah[h]);                // tanh(x) = 1 - 2/(e^{2x}+1)
        float th = 1.0f - 2.0f / (e2 + 1.0f);
        float v  = (1.0f - z) * th;                     // H_new = (1-Z)*H_tilde  (H == 0)
        v = fmaxf(v, 0.0f);                             // relu
        o = fmaf(v, sWl[h], o);                         // @ W_lin
    }
    out[i] = o;
}

// ---------------------------------------------------------------- launch
//
// Algebra (reference runs ONE GRU step from H = 0):
//   _cheb(H, *) = bias only;  H*R = 0 -> _cheb(H*R, W_hh) = b_hh
//   H_new = (1-Z)*H_tilde
// => only W_xz, W_xh, biases bxz/bhz/bxh/bhh, W_lin/b_lin are live.
//
// Input order: 0 x, 1 edge_index(int32), 2 edge_weight, 3 W_xz, 4 b_xz,
// 5 W_hz, 6 b_hz, 7 W_xr, 8 b_xr, 9 W_hr, 10 b_hr, 11 W_xh, 12 b_xh,
// 13 W_hh, 14 b_hh, 15 W_lin, 16 b_lin
extern "C" void kernel_launch(void* const* d_in, const int* in_sizes, int n_in,
                              void* d_out, int out_size) {
    const float* x  = (const float*)d_in[0];
    const int*   ei = (const int*)d_in[1];
    const float* ew = (const float*)d_in[2];

    int n = in_sizes[0] / FEAT;     // 100000
    int E = in_sizes[2];            // 3200000
    const int* src = ei;            // edge_index[0]
    const int* dst = ei + E;        // edge_index[1]

    const int T = 256;
    long long NT = (long long)E * 4;          // 4 lanes per edge
    k_zero     <<<(n * FEAT + T - 1) / T, T>>>(n * FEAT, n);
    k_deg      <<<(E + T - 1) / T, T>>>(src, ew, E);
    k_dis_scale<<<(n + T - 1) / T, T>>>((const float4*)x, n);
    k_scatter  <<<(int)((NT + T - 1) / T), T>>>(src, dst, ew, NT);
    k_node     <<<(n + 127) / 128, 128>>>((const float4*)x,
                                          (const float*)d_in[3],  (const float*)d_in[4],
                                          (const float*)d_in[6],  (const float*)d_in[11],
                                          (const float*)d_in[12], (const float*)d_in[14],
                                          (const float*)d_in[15], (const float*)d_in[16],
                                          (float*)d_out, n);
}

// round 12
// speedup vs baseline: 1.4055x; 1.0109x over previous
#include <cuda_runtime.h>
#include <cuda_bf16.h>

#define NODES 100000
#define FEAT  16
#define HID   32

// Scratch (allocation-free rule: __device__ globals)
__device__ __align__(16) float g_deg[NODES];
__device__ __align__(16) float g_dis[NODES];
__device__ __align__(16) float g_xs [NODES * FEAT];   // x'[i] = dis[i] * x[i]
__device__ __align__(16) float g_u  [NODES * FEAT];   // u[d] = sum_e w * x'[src]

// Blackwell packed FFMA2 (PTX-only; SASS_QUICKREF: fma.rn.f32x2)
#define FMA2(acc, w2, s2) \
    asm("fma.rn.f32x2 %0, %1, %2, %0;" : "+l"(acc) : "l"(w2), "l"(s2))

__device__ __forceinline__ unsigned long long pack2(float v) {
    unsigned long long r;
    unsigned int b = __float_as_uint(v);
    asm("mov.b64 %0, {%1, %1};" : "=l"(r) : "r"(b));
    return r;
}

// ---------------------------------------------------------------- zero g_deg (tiny)
__global__ void k_zero(int n) {
    int i = blockIdx.x * blockDim.x + threadIdx.x;
    if (i < n) g_deg[i] = 0.0f;
}

// ---------------------------------------------------------------- deg = segsum(w, src), 4 edges/thread
__global__ void k_deg(const int4* __restrict__ src4,
                      const float4* __restrict__ w4, int n4) {
    int i = blockIdx.x * blockDim.x + threadIdx.x;
    if (i >= n4) return;
    int4   s  = __ldg(&src4[i]);
    float4 wv = __ldg(&w4[i]);
    atomicAdd(&g_deg[s.x], wv.x);
    atomicAdd(&g_deg[s.y], wv.y);
    atomicAdd(&g_deg[s.z], wv.z);
    atomicAdd(&g_deg[s.w], wv.w);
}

// ---------------------------------------------------------------- dis = rsqrt(deg); x' = dis*x; u = 0
__global__ void k_dis_scale(const float4* __restrict__ x4, int n) {
    int i = blockIdx.x * blockDim.x + threadIdx.x;
    if (i >= n) return;
    float d  = g_deg[i];
    float di = (d > 0.0f) ? rsqrtf(fmaxf(d, 1e-12f)) : 0.0f;
    g_dis[i] = di;
    float4* xs4 = reinterpret_cast<float4*>(g_xs) + (size_t)i * 4;
    float4* u4  = reinterpret_cast<float4*>(g_u)  + (size_t)i * 4;
    const float4 z4 = make_float4(0.f, 0.f, 0.f, 0.f);
#pragma unroll
    for (int q = 0; q < 4; q++) {
        float4 v = __ldg(&x4[(size_t)i * 4 + q]);
        v.x *= di; v.y *= di; v.z *= di; v.w *= di;
        xs4[q] = v;
        u4[q]  = z4;
    }
}

// ---------------------------------------------------------------- u[d] += w * x'[src]
// Cooperative scatter: 4 lanes per edge, lane j owns 16B chunk j of the 64B row.
// ~2.4 L1tex wavefronts/edge — structural floor for this layout (R8-calibrated).
__global__ void k_scatter(const int* __restrict__ src,
                          const int* __restrict__ dst,
                          const float* __restrict__ w, long long NT) {
    long long tid = (long long)blockIdx.x * blockDim.x + threadIdx.x;
    if (tid >= NT) return;
    int e = (int)(tid >> 2);
    int j = (int)(tid & 3);
    int s = __ldg(&src[e]);
    int d = __ldg(&dst[e]);
    float we = __ldg(&w[e]);
    float4 v = __ldg(reinterpret_cast<const float4*>(g_xs) + (size_t)s * 4 + j);
    float* o = g_u + (size_t)d * FEAT + j * 4;
    asm volatile("red.global.add.v4.f32 [%0], {%1, %2, %3, %4};"
                 :: "l"(o),
                    "f"(we * v.x), "f"(we * v.y), "f"(we * v.z), "f"(we * v.w)
                 : "memory");
}

// ---------------------------------------------------------------- per-node gates + readout
// tx1[i] = -dis[i]*u[i]; GEMVs in packed f32x2 (2 MACs/instr) with LDS.128
// weight reads -> fma-pipe issue time halves vs scalar FFMA.
__global__ void __launch_bounds__(128) k_node(const float4* __restrict__ x4,
                                              const float* __restrict__ Wxz,   // [2][16][32]
                                              const float* __restrict__ bxz,
                                              const float* __restrict__ bhz,
                                              const float* __restrict__ Wxh,   // [2][16][32]
                                              const float* __restrict__ bxh,
                                              const float* __restrict__ bhh,
                                              const float* __restrict__ Wlin,  // [32]
                                              const float* __restrict__ blin,  // [1]
                                              float* __restrict__ out, int n) {
    __shared__ __align__(16) float sWz[2 * FEAT * HID];   // 1024 floats
    __shared__ __align__(16) float sWh[2 * FEAT * HID];
    __shared__ __align__(16) float sbz[HID];              // bxz + bhz
    __shared__ __align__(16) float sbh[HID];              // bxh + bhh
    __shared__ __align__(16) float sWl[HID];
    __shared__ float sbl;

    int t = threadIdx.x;
    for (int k = t; k < 2 * FEAT * HID; k += 128) {
        sWz[k] = __ldg(&Wxz[k]);
        sWh[k] = __ldg(&Wxh[k]);
    }
    if (t < HID) {
        sbz[t] = __ldg(&bxz[t]) + __ldg(&bhz[t]);
        sbh[t] = __ldg(&bxh[t]) + __ldg(&bhh[t]);
        sWl[t] = __ldg(&Wlin[t]);
    }
    if (t == 0) sbl = __ldg(&blin[0]);
    __syncthreads();

    int i = blockIdx.x * blockDim.x + t;
    if (i >= n) return;

    float ndis = -g_dis[i];

    float xr[FEAT], tr[FEAT];
#pragma unroll
    for (int q = 0; q < 4; q++) {
        float4 v = __ldg(&x4[(size_t)i * 4 + q]);
        xr[4 * q + 0] = v.x; xr[4 * q + 1] = v.y; xr[4 * q + 2] = v.z; xr[4 * q + 3] = v.w;
        float4 tv = reinterpret_cast<const float4*>(g_u)[(size_t)i * 4 + q];
        tr[4 * q + 0] = ndis * tv.x; tr[4 * q + 1] = ndis * tv.y;
        tr[4 * q + 2] = ndis * tv.z; tr[4 * q + 3] = ndis * tv.w;
    }

    // Packed accumulators: HID/2 = 16 f32x2 pairs each
    unsigned long long az2[HID / 2], ah2[HID / 2];
    const unsigned long long* sbz2 = reinterpret_cast<const unsigned long long*>(sbz);
    const unsigned long long* sbh2 = reinterpret_cast<const unsigned long long*>(sbh);
#pragma unroll
    for (int p = 0; p < HID / 2; p++) {
        az2[p] = sbz2[p];
        ah2[p] = sbh2[p];
    }

    const ulonglong2* sWz2 = reinterpret_cast<const ulonglong2*>(sWz);  // 4 floats per elt
    const ulonglong2* sWh2 = reinterpret_cast<const ulonglong2*>(sWh);
#pragma unroll
    for (int c = 0; c < FEAT; c++) {
        unsigned long long xc2 = pack2(xr[c]);
        unsigned long long tc2 = pack2(tr[c]);
        int r0 = c * (HID / 4);               // W[0][c][:] as ulonglong2
        int r1 = (FEAT + c) * (HID / 4);      // W[1][c][:]
#pragma unroll
        for (int q = 0; q < HID / 4; q++) {
            ulonglong2 a = sWz2[r0 + q];
            ulonglong2 b = sWz2[r1 + q];
            ulonglong2 p = sWh2[r0 + q];
            ulonglong2 r = sWh2[r1 + q];
            FMA2(az2[2 * q + 0], a.x, xc2);
            FMA2(az2[2 * q + 1], a.y, xc2);
            FMA2(az2[2 * q + 0], b.x, tc2);
            FMA2(az2[2 * q + 1], b.y, tc2);
            FMA2(ah2[2 * q + 0], p.x, xc2);
            FMA2(ah2[2 * q + 1], p.y, xc2);
            FMA2(ah2[2 * q + 0], r.x, tc2);
            FMA2(ah2[2 * q + 1], r.y, tc2);
        }
    }

    float o = sbl;
#pragma unroll
    for (int p = 0; p < HID / 2; p++) {
        unsigned int zlo, zhi, hlo, hhi;
        asm("mov.b64 {%0, %1}, %2;" : "=r"(zlo), "=r"(zhi) : "l"(az2[p]));
        asm("mov.b64 {%0, %1}, %2;" : "=r"(hlo), "=r"(hhi) : "l"(ah2[p]));
        float azv[2] = { __uint_as_float(zlo), __uint_as_float(zhi) };
        float ahv[2] = { __uint_as_float(hlo), __uint_as_float(hhi) };
#pragma unroll
        for (int k = 0; k < 2; k++) {
            float z  = 1.0f / (1.0f + __expf(-azv[k]));     // sigmoid
            float e2 = __expf(2.0f * ahv[k]);               // tanh(x) = 1 - 2/(e^{2x}+1)
            float th = 1.0f - 2.0f / (e2 + 1.0f);
            float v  = (1.0f - z) * th;                     // H_new = (1-Z)*H_tilde (H==0)
            v = fmaxf(v, 0.0f);                             // relu
            o = fmaf(v, sWl[2 * p + k], o);                 // @ W_lin
        }
    }
    out[i] = o;
}

// ---------------------------------------------------------------- launch
//
// Algebra (ONE GRU step from H = 0): _cheb(H,*) = bias; H*R = 0;
// H_new = (1-Z)*H_tilde => only W_xz, W_xh, bxz/bhz/bxh/bhh, W_lin/b_lin live.
//
// Input order: 0 x, 1 edge_index(int32), 2 edge_weight, 3 W_xz, 4 b_xz,
// 5 W_hz, 6 b_hz, 7 W_xr, 8 b_xr, 9 W_hr, 10 b_hr, 11 W_xh, 12 b_xh,
// 13 W_hh, 14 b_hh, 15 W_lin, 16 b_lin
extern "C" void kernel_launch(void* const* d_in, const int* in_sizes, int n_in,
                              void* d_out, int out_size) {
    const float* x  = (const float*)d_in[0];
    const int*   ei = (const int*)d_in[1];
    const float* ew = (const float*)d_in[2];

    int n = in_sizes[0] / FEAT;     // 100000
    int E = in_sizes[2];            // 3200000 (divisible by 4)
    const int* src = ei;            // edge_index[0]
    const int* dst = ei + E;        // edge_index[1]

    const int T = 256;
    int n4 = E / 4;
    long long NT = (long long)E * 4;          // 4 lanes per edge
    k_zero     <<<(n + T - 1) / T, T>>>(n);
    k_deg      <<<(n4 + T - 1) / T, T>>>((const int4*)src, (const float4*)ew, n4);
    k_dis_scale<<<(n + T - 1) / T, T>>>((const float4*)x, n);
    k_scatter  <<<(int)((NT + T - 1) / T), T>>>(src, dst, ew, NT);
    k_node     <<<(n + 127) / 128, 128>>>((const float4*)x,
                                          (const float*)d_in[3],  (const float*)d_in[4],
                                          (const float*)d_in[6],  (const float*)d_in[11],
                                          (const float*)d_in[12], (const float*)d_in[14],
                                          (const float*)d_in[15], (const float*)d_in[16],
                                          (float*)d_out, n);
}